// round 11
// baseline (speedup 1.0000x reference)
#include <cuda_runtime.h>
#include <cuda_bf16.h>
#include <cstdint>

// Problem constants (fixed by setup_inputs)
#define BB 8
#define LL 8192
#define DD 1024
#define D4 (DD / 4)
#define ROWS_PER_BLK 4

// Scratch (persistent __device__ globals; rewritten fully every launch)
__device__ int g_src[BB * LL];    // gather index: source row for each dest row
__device__ int g_numtok[BB];      // boundary-token count per batch

// ---------------------------------------------------------------------------
// Kernel 1: per-batch stable-partition -> gather index g_src[b*LL+dest]=src.
// 1024 threads, 8 elems each. Dest-permutation scatter staged in SMEM,
// then written out as coalesced int4 stores. Only 8 CTAs exist, so the
// 32KB smem costs nothing.
// ---------------------------------------------------------------------------
__global__ __launch_bounds__(1024) void scan_kernel(const void* __restrict__ mask) {
    const int b = blockIdx.x;
    const int t = threadIdx.x;
    const int lane = t & 31;
    const int warp = t >> 5;
    const int base = t * 8;

    __shared__ int sh_src[LL];      // 32KB staging

    // dtype detect: warp 0 probes first 128 bytes of batch 0.
    // Wide-word bool (i32/fp32) has zero bytes at odd offsets; u8 bool
    // has ~50% nonzero there (false-positive prob ~2^-64).
    __shared__ int sh_interp;
    if (warp == 0) {
        const uchar4 c = ((const uchar4*)mask)[lane];
        int odd = c.y + c.w;
#pragma unroll
        for (int off = 16; off > 0; off >>= 1)
            odd += __shfl_down_sync(0xffffffffu, odd, off);
        if (lane == 0) sh_interp = (odd == 0) ? 1 : 0;
    }
    __syncthreads();
    const int interp = sh_interp;

    // 8 elements per thread -> bitmask
    unsigned int mbits = 0;
    if (interp) {
        const int4* p = (const int4*)((const int*)mask + (size_t)b * LL + base);
        const int4 a = p[0], c = p[1];
        mbits |= (a.x ? 1u : 0u) | ((a.y ? 1u : 0u) << 1) |
                 ((a.z ? 1u : 0u) << 2) | ((a.w ? 1u : 0u) << 3);
        mbits |= ((c.x ? 1u : 0u) << 4) | ((c.y ? 1u : 0u) << 5) |
                 ((c.z ? 1u : 0u) << 6) | ((c.w ? 1u : 0u) << 7);
    } else {
        const uint2 u = *(const uint2*)((const unsigned char*)mask + (size_t)b * LL + base);
#pragma unroll
        for (int k = 0; k < 4; k++) {
            mbits |= (((u.x >> (8 * k)) & 0xffu) ? 1u : 0u) << k;
            mbits |= (((u.y >> (8 * k)) & 0xffu) ? 1u : 0u) << (4 + k);
        }
    }
    const int s = __popc(mbits);

    // warp-inclusive scan of per-thread sums
    int ws = s;
#pragma unroll
    for (int off = 1; off < 32; off <<= 1) {
        int v = __shfl_up_sync(0xffffffffu, ws, off);
        if (lane >= off) ws += v;
    }

    __shared__ int wsum[32];
    if (lane == 31) wsum[warp] = ws;
    __syncthreads();

    __shared__ int woff[32];
    __shared__ int s_total;
    if (warp == 0) {
        int v = wsum[lane];
        int wv = v;
#pragma unroll
        for (int off = 1; off < 32; off <<= 1) {
            int u = __shfl_up_sync(0xffffffffu, wv, off);
            if (lane >= off) wv += u;
        }
        woff[lane] = wv - v;
        if (lane == 31) s_total = wv;
    }
    __syncthreads();

    const int total = s_total;
    int pref = woff[warp] + ws - s;  // exclusive prefix for this thread
    if (t == 0) g_numtok[b] = total;

    // SMEM scatter
#pragma unroll
    for (int i = 0; i < 8; i++) {
        const int bit = (mbits >> i) & 1u;
        const int idx = base + i;
        const int dest = bit ? pref : (total + (idx - pref));
        sh_src[dest] = idx;
        pref += bit;
    }
    __syncthreads();

    // Coalesced copy-out: 2048 int4 stores, 2 per thread
    {
        const int4* s4 = (const int4*)sh_src;
        int4* d4 = (int4*)(g_src + b * LL);
        d4[t] = s4[t];
        d4[1024 + t] = s4[1024 + t];
    }

    // PDL: allow the dependent gather grid to pass its gridsync.
    cudaTriggerProgrammaticLaunchCompletion();
}

// ---------------------------------------------------------------------------
// Kernel 2: gather 4 dest rows per block + write mask elements.
// Plain LDG (preserve cross-replay L2 read residency) + STG.cs stores
// (streaming writes evict-first so they do NOT evict the read set).
// Barrier-free prologue: every thread reads the 8 numtok words directly
// (uniform broadcast, L1-hit) instead of smem + 2x syncthreads.
// ---------------------------------------------------------------------------
__global__ __launch_bounds__(256) void gather_kernel(const float4* __restrict__ in,
                                                     float4* __restrict__ out,
                                                     long out_size) {
    const int b = blockIdx.y;
    const int r0 = blockIdx.x * ROWS_PER_BLK;
    const int t = threadIdx.x;

    const float4* inb = in + (size_t)b * LL * D4;   // prologue, pre-gridsync

    cudaGridDependencySynchronize();

    // S = max(numtok) without barriers: two int4 broadcast loads
    const int4 n0 = *(const int4*)&g_numtok[0];
    const int4 n1 = *(const int4*)&g_numtok[4];
    const int ntb = ((const int*)&n0)[0] * 0 +   // (avoid unused warnings pattern)
                    ((b < 4) ? ((const int*)&n0)[b & 3] : ((const int*)&n1)[b & 3]);
    int S = max(max(max(n0.x, n0.y), max(n0.z, n0.w)),
                max(max(n1.x, n1.y), max(n1.z, n1.w)));

    if (r0 >= S) return;

    const int4 sr = *(const int4*)&g_src[b * LL + r0];  // 16B-aligned (r0 % 4 == 0)
    const int nrows = min(ROWS_PER_BLK, S - r0);

    float4* outb = out + ((size_t)b * S + r0) * D4;

    // mask elements for these rows first (off the critical tail)
    if (t < ROWS_PER_BLK) {
        const int row = r0 + t;
        if (row < S) {
            const long mbase = (long)BB * S * DD;
            const long rem = out_size - mbase;
            const int val = (row < ntb) ? 1 : 0;
            const long k = (long)b * S + row;
            float* outf = (float*)out;
            if (rem >= (long)BB * S) {
                outf[mbase + k] = (float)val;
            } else if (rem * 4 >= (long)BB * S) {
                ((unsigned char*)(outf + mbase))[k] = (unsigned char)val;
            }
        }
    }

    float4 v0, v1, v2, v3;
    v0 = inb[(size_t)sr.x * D4 + t];
    if (nrows > 1) v1 = inb[(size_t)sr.y * D4 + t];
    if (nrows > 2) v2 = inb[(size_t)sr.z * D4 + t];
    if (nrows > 3) v3 = inb[(size_t)sr.w * D4 + t];

    __stcs(&outb[t], v0);
    if (nrows > 1) __stcs(&outb[D4 + t], v1);
    if (nrows > 2) __stcs(&outb[2 * D4 + t], v2);
    if (nrows > 3) __stcs(&outb[3 * D4 + t], v3);
}

extern "C" void kernel_launch(void* const* d_in, const int* in_sizes, int n_in,
                              void* d_out, int out_size) {
    const float* hidden = (const float*)d_in[0];
    const void* bmask = d_in[1];
    float* out = (float*)d_out;

    // Upper bound on S from output size (exact S derived on-device).
    long os = (long)out_size;
    int rows_ub = (int)((os + (long)BB * DD - 1) / ((long)BB * DD));
    if (rows_ub > LL) rows_ub = LL;
    if (rows_ub < 1) rows_ub = 1;

    scan_kernel<<<BB, 1024>>>(bmask);

    // Gather with programmatic dependent launch (overlap with scan)
    cudaLaunchConfig_t cfg = {};
    cfg.gridDim = dim3((rows_ub + ROWS_PER_BLK - 1) / ROWS_PER_BLK, BB, 1);
    cfg.blockDim = dim3(256, 1, 1);
    cfg.dynamicSmemBytes = 0;
    cfg.stream = 0;
    cudaLaunchAttribute attr[1];
    attr[0].id = cudaLaunchAttributeProgrammaticStreamSerialization;
    attr[0].val.programmaticStreamSerializationAllowed = 1;
    cfg.attrs = attr;
    cfg.numAttrs = 1;
    cudaLaunchKernelEx(&cfg, gather_kernel, (const float4*)hidden, (float4*)out, os);
}